// round 5
// baseline (speedup 1.0000x reference)
#include <cuda_runtime.h>

typedef unsigned long long ull;

#define S_LEN 2048
#define B_SZ 32
#define H_SZ 256
#define COLS 1024

__device__ float g_xg[(size_t)B_SZ * S_LEN * COLS];   // [b*S+s][gate*256+j], gate order f,i,c,o
__device__ float g_h[2][B_SZ][H_SZ];
__device__ unsigned int g_arrive[4];

__device__ __forceinline__ ull fma2(ull a, ull b, ull c){
  ull d; asm("fma.rn.f32x2 %0, %1, %2, %3;" : "=l"(d) : "l"(a), "l"(b), "l"(c)); return d;
}
__device__ __forceinline__ ull dup2(float x){
  ull d; asm("mov.b64 %0, {%1, %1};" : "=l"(d) : "f"(x)); return d;
}
__device__ __forceinline__ void unpack2(ull v, float& lo, float& hi){
  asm("mov.b64 {%0, %1}, %2;" : "=f"(lo), "=f"(hi) : "l"(v));
}
__device__ __forceinline__ float sigmoidf_(float x){ return 1.f / (1.f + __expf(-x)); }

__global__ void init_state(){
  int tid = blockIdx.x * blockDim.x + threadIdx.x;
  float* hz = (float*)g_h;
  if (tid < 2 * B_SZ * H_SZ) hz[tid] = 0.f;
  if (tid < 4) g_arrive[tid] = 0u;
}

// ---------------- kernel 1: xg = x @ W + b (fp32x2 GEMM, 128x64x32 tiles) ----------------
__global__ __launch_bounds__(256, 2) void xw_gemm(
    const float* __restrict__ x,
    const float* __restrict__ Wf, const float* __restrict__ Wi,
    const float* __restrict__ Wc, const float* __restrict__ Wo,
    const float* __restrict__ bf, const float* __restrict__ bi,
    const float* __restrict__ bc, const float* __restrict__ bo)
{
  __shared__ float A_s[32][132];
  __shared__ float B_s[32][68];
  const int r0 = blockIdx.x * 128;
  const int c0 = blockIdx.y * 64;
  const int gate = c0 >> 8, j0 = c0 & 255;
  const float* Wg; const float* bg;
  if (gate == 0){ Wg = Wf; bg = bf; } else if (gate == 1){ Wg = Wi; bg = bi; }
  else if (gate == 2){ Wg = Wc; bg = bc; } else { Wg = Wo; bg = bo; }

  const int tid = threadIdx.x;
  const int tx = tid & 15, ty = tid >> 4;
  const int arow = tid >> 3, ak = (tid & 7) * 4;

  ull acc[4][4];
  #pragma unroll
  for (int i = 0; i < 4; i++)
    #pragma unroll
    for (int j = 0; j < 4; j++) acc[i][j] = 0ull;

  for (int kc = 0; kc < 256; kc += 32){
    #pragma unroll
    for (int i = 0; i < 4; i++){
      float4 v = *(const float4*)&x[(size_t)(r0 + arow + i*32) * 256 + kc + ak];
      A_s[ak+0][arow + i*32] = v.x; A_s[ak+1][arow + i*32] = v.y;
      A_s[ak+2][arow + i*32] = v.z; A_s[ak+3][arow + i*32] = v.w;
    }
    #pragma unroll
    for (int j = 0; j < 2; j++){
      int e = tid + j*256, kk = e >> 4, nn = (e & 15) * 4;
      *(float4*)&B_s[kk][nn] = *(const float4*)&Wg[(size_t)(kc + kk) * 256 + j0 + nn];
    }
    __syncthreads();
    #pragma unroll
    for (int k = 0; k < 32; k++){
      ulonglong2 a01 = *(const ulonglong2*)&A_s[k][ty*8];
      ulonglong2 a23 = *(const ulonglong2*)&A_s[k][ty*8 + 4];
      float4 bq = *(const float4*)&B_s[k][tx*4];
      ull bb0 = dup2(bq.x), bb1 = dup2(bq.y), bb2 = dup2(bq.z), bb3 = dup2(bq.w);
      ull av[4] = {a01.x, a01.y, a23.x, a23.y};
      #pragma unroll
      for (int i = 0; i < 4; i++){
        acc[i][0] = fma2(av[i], bb0, acc[i][0]);
        acc[i][1] = fma2(av[i], bb1, acc[i][1]);
        acc[i][2] = fma2(av[i], bb2, acc[i][2]);
        acc[i][3] = fma2(av[i], bb3, acc[i][3]);
      }
    }
    __syncthreads();
  }

  float bias[4];
  #pragma unroll
  for (int j = 0; j < 4; j++) bias[j] = bg[j0 + tx*4 + j];
  #pragma unroll
  for (int i = 0; i < 4; i++){
    float lo[4], hi[4];
    #pragma unroll
    for (int j = 0; j < 4; j++) unpack2(acc[i][j], lo[j], hi[j]);
    size_t base = (size_t)(r0 + ty*8 + 2*i) * COLS + c0 + tx*4;
    *(float4*)&g_xg[base]        = make_float4(lo[0]+bias[0], lo[1]+bias[1], lo[2]+bias[2], lo[3]+bias[3]);
    *(float4*)&g_xg[base + COLS] = make_float4(hi[0]+bias[0], hi[1]+bias[1], hi[2]+bias[2], hi[3]+bias[3]);
  }
}

// ---------------- kernel 2: persistent recurrence ----------------
// 128 CTAs = 4 groups (8 batches) x 32 CTAs (8 units x 4 gates = 32 cols).
// warp = k-slice (32 k), lane = local gate-col. Barrier per step per group.
#define KPAD 260

__global__ __launch_bounds__(256, 1) void lstm_rec(
    const float* __restrict__ Uf, const float* __restrict__ Ui,
    const float* __restrict__ Uc, const float* __restrict__ Uo,
    float* __restrict__ out, int out_size)
{
  __shared__ float U_s[32][KPAD];          // [col][k]
  __shared__ union { float h[8][256]; float red[2304]; } sh;  // red[ks*288 + c*9 + b]

  const int tid = threadIdx.x;
  const int w = tid >> 5, lane = tid & 31;
  const int cta = blockIdx.x, grp = cta >> 5, m = cta & 31;
  const int j0 = m * 8;

  // stage U slice: col c -> gate c>>3, unit c&7
  for (int e = tid; e < 32 * 256; e += 256){
    int c = e & 31, k = e >> 5;
    int g = c >> 3, u = c & 7;
    const float* Ug = (g == 0) ? Uf : (g == 1) ? Ui : (g == 2) ? Uc : Uo;
    U_s[c][k] = Ug[k * 256 + j0 + u];
  }
  __syncthreads();

  const int bb = tid >> 3, uu = tid & 7;        // valid when tid < 64
  const int gb = grp * 8 + bb;
  float cst = 0.f, hlast = 0.f;

  for (int s = 0; s < S_LEN; s++){
    const int p = s & 1, pn = p ^ 1;

    // prefetch xg (in flight during matvec)
    float xg0 = 0.f, xg1 = 0.f, xg2 = 0.f, xg3 = 0.f;
    if (tid < 64){
      const float* xp = &g_xg[((size_t)gb * S_LEN + s) * COLS + j0 + uu];
      xg0 = __ldg(xp); xg1 = __ldg(xp + 256); xg2 = __ldg(xp + 512); xg3 = __ldg(xp + 768);
    }
    // cooperative h load: 2048 floats
    {
      int b = tid >> 5, k8 = (tid & 31) * 8;
      float4 v0 = *(const float4*)&g_h[p][grp*8 + b][k8];
      float4 v1 = *(const float4*)&g_h[p][grp*8 + b][k8 + 4];
      *(float4*)&sh.h[b][k8]     = v0;
      *(float4*)&sh.h[b][k8 + 4] = v1;
    }
    __syncthreads();

    // matvec partials: this thread = (k-slice w, col lane)
    ull acc2[8];
    #pragma unroll
    for (int b = 0; b < 8; b++) acc2[b] = 0ull;
    const int kb = w * 32;
    #pragma unroll
    for (int j = 0; j < 32; j += 4){
      ulonglong2 uv = *(const ulonglong2*)&U_s[lane][kb + j];
      #pragma unroll
      for (int b = 0; b < 8; b++){
        ulonglong2 hv = *(const ulonglong2*)&sh.h[b][kb + j];
        acc2[b] = fma2(hv.x, uv.x, acc2[b]);
        acc2[b] = fma2(hv.y, uv.y, acc2[b]);
      }
    }
    __syncthreads();   // protect h/red union
    #pragma unroll
    for (int b = 0; b < 8; b++){
      float lo, hi; unpack2(acc2[b], lo, hi);
      sh.red[w*288 + lane*9 + b] = lo + hi;
    }
    __syncthreads();

    // gates: threads 0..63 = (batch bb, unit uu)
    if (tid < 64){
      float z[4] = {xg0, xg1, xg2, xg3};
      #pragma unroll
      for (int g = 0; g < 4; g++){
        float sum = z[g];
        #pragma unroll
        for (int ks = 0; ks < 8; ks++) sum += sh.red[ks*288 + (g*8 + uu)*9 + bb];
        z[g] = sum;
      }
      float f  = sigmoidf_(z[0]);
      float ii = sigmoidf_(z[1]);
      float gg = tanhf(z[2]);
      float oo = sigmoidf_(z[3]);
      cst = f * cst + ii * gg;
      hlast = oo * tanhf(cst);
      g_h[pn][gb][j0 + uu] = hlast;
      out[((size_t)gb * S_LEN + s) * 256 + j0 + uu] = hlast;
    }
    __syncthreads();
    if (tid == 0){
      __threadfence();
      atomicAdd(&g_arrive[grp], 1u);
      unsigned int target = 32u * (unsigned int)(s + 1), v;
      do {
        asm volatile("ld.acquire.gpu.u32 %0, [%1];" : "=r"(v) : "l"(&g_arrive[grp]));
      } while (v < target);
    }
    __syncthreads();
  }

  // final (h_T, c_T), appended after hidden_seq if the output carries them
  if (tid < 64 && out_size >= 16777216 + 16384){
    size_t base = (size_t)16777216 + (size_t)gb * 256 + j0 + uu;
    out[base]        = hlast;
    out[base + 8192] = cst;
  }
}

extern "C" void kernel_launch(void* const* d_in, const int* in_sizes, int n_in,
                              void* d_out, int out_size) {
  const float* x  = (const float*)d_in[0];
  const float* Wf = (const float*)d_in[1];
  const float* Uf = (const float*)d_in[2];
  const float* bf = (const float*)d_in[3];
  const float* Wi = (const float*)d_in[4];
  const float* Ui = (const float*)d_in[5];
  const float* bi = (const float*)d_in[6];
  const float* Wo = (const float*)d_in[7];
  const float* Uo = (const float*)d_in[8];
  const float* bo = (const float*)d_in[9];
  const float* Wc = (const float*)d_in[10];
  const float* Uc = (const float*)d_in[11];
  const float* bc = (const float*)d_in[12];
  float* out = (float*)d_out;

  init_state<<<64, 256>>>();
  dim3 g1(512, 16);
  xw_gemm<<<g1, 256>>>(x, Wf, Wi, Wc, Wo, bf, bi, bc, bo);
  lstm_rec<<<128, 256>>>(Uf, Ui, Uc, Uo, out, out_size);
}